// round 10
// baseline (speedup 1.0000x reference)
#include <cuda_runtime.h>
#include <cstdint>

#define B_   4
#define H_   8
#define LQ   1024
#define DH   64
#define KL   1024
#define NJ   33      // 2*MAX_REL_POS + 1
#define NJP  36      // padded j extent (9 groups of 4)
#define MAXREL 16
#define QT   2       // q-rows per block
#define SPAD 36      // sS row stride (16B-aligned rows: 144B)

// ---------------------------------------------------------------------------
// Fused: per block (2 q-rows, batch b):
//   A) load table (transposed -> tT[d][j]) + query[2][8][64] to smem
//   B) S[ql][h][j] register-tiled: 144 threads, each (ql,h,4j);
//      per d: 1 LDS.128 + 1 broadcast LDS + 4 FMA
//   C) out[b,h,q,k] = S[ql][h][clip(ts[k]-ts[q])+16]   (round-3 gather body)
// ---------------------------------------------------------------------------
__global__ void __launch_bounds__(256, 6) fused_relpe_kernel(
    const float* __restrict__ query,
    const float* __restrict__ table,
    const int*   __restrict__ time_ids,
    float* __restrict__ out)
{
    __shared__ __align__(16) float tT[DH][NJP];      // transposed table [d][j]
    __shared__ __align__(16) float qS[QT][H_][DH];   // query rows, d-contig
    __shared__ __align__(16) float sS[QT][H_][SPAD]; // S values
    __shared__ int   s_tq[QT];

    const int tid   = threadIdx.x;
    const int qBase = blockIdx.x * QT;
    const int b     = blockIdx.y;

    // --- Phase A: loads ---
    // table: 528 float4 reads, scatter-transpose into tT[d][j]
    for (int i = tid; i < NJ * DH / 4; i += 256) {
        float4 v = ((const float4*)table)[i];
        int j  = i >> 4;
        int d0 = (i & 15) << 2;
        tT[d0 + 0][j] = v.x; tT[d0 + 1][j] = v.y;
        tT[d0 + 2][j] = v.z; tT[d0 + 3][j] = v.w;
    }
    // zero pad j = 33..35
    for (int i = tid; i < DH * 3; i += 256) tT[i / 3][NJ + (i % 3)] = 0.f;
    // query: 256 float4
    for (int i = tid; i < QT * H_ * DH / 4; i += 256) {
        int h  = i >> 5;
        int r  = i & 31;
        int ql = r >> 4;
        int d0 = (r & 15) << 2;
        float4 v = *(const float4*)(query +
            (size_t)(((b * H_ + h) << 10) + qBase + ql) * DH + d0);
        *(float4*)(&qS[ql][h][d0]) = v;
    }
    const int* tsb = time_ids + b * KL;
    if (tid < QT) s_tq[tid] = tsb[qBase + tid];
    __syncthreads();

    // --- Phase B: register-tiled dots ---
    // 144 threads: t = ql*72 + h*9 + jg;  each computes S[ql][h][jg*4 .. +3]
    if (tid < QT * H_ * 9) {
        const int jg = tid % 9;
        const int h  = (tid / 9) & 7;
        const int ql = tid / 72;
        const int j0 = jg * 4;

        float a0 = 0.f, a1 = 0.f, a2 = 0.f, a3 = 0.f;
        #pragma unroll 8
        for (int d = 0; d < DH; d++) {
            float4 tv = *(const float4*)(&tT[d][j0]);
            float  qv = qS[ql][h][d];
            a0 += qv * tv.x;
            a1 += qv * tv.y;
            a2 += qv * tv.z;
            a3 += qv * tv.w;
        }
        *(float4*)(&sS[ql][h][j0]) = make_float4(a0, a1, a2, a3);
    }
    __syncthreads();

    // --- Phase C: gather + store (round-3 body) ---
    const int k0 = tid * 4;
    const int4 tk = *(const int4*)(tsb + k0);

    #pragma unroll
    for (int ql = 0; ql < QT; ql++) {
        const int tq = s_tq[ql];
        int i0 = min(max(tk.x - tq, -MAXREL), MAXREL) + MAXREL;
        int i1 = min(max(tk.y - tq, -MAXREL), MAXREL) + MAXREL;
        int i2 = min(max(tk.z - tq, -MAXREL), MAXREL) + MAXREL;
        int i3 = min(max(tk.w - tq, -MAXREL), MAXREL) + MAXREL;

        float* op = out + ((size_t)(((b * H_) << 10) + qBase + ql) << 10) + k0;
        #pragma unroll
        for (int h = 0; h < H_; h++) {
            float4 o = make_float4(sS[ql][h][i0], sS[ql][h][i1],
                                   sS[ql][h][i2], sS[ql][h][i3]);
            *(float4*)(op + ((size_t)h << 20)) = o;
        }
    }
}

// ---------------------------------------------------------------------------
extern "C" void kernel_launch(void* const* d_in, const int* in_sizes, int n_in,
                              void* d_out, int out_size)
{
    const float* query    = (const float*)d_in[0];   // [4,8,1024,64]
    const float* table    = (const float*)d_in[1];   // [33,64]
    const int*   time_ids = (const int*)d_in[2];     // [4,1024] int32
    float*       out      = (float*)d_out;           // [4,8,1024,1024]

    dim3 grid(LQ / QT, B_);
    fused_relpe_kernel<<<grid, 256>>>(query, table, time_ids, out);
}

// round 11
// speedup vs baseline: 1.0146x; 1.0146x over previous
#include <cuda_runtime.h>
#include <cstdint>

#define B_   4
#define H_   8
#define LQ   1024
#define DH   64
#define KL   1024
#define NJ   33      // 2*MAX_REL_POS + 1
#define NJP  36      // padded stride for S
#define MAXREL 16
#define QROWS 64     // q-rows per kernel1 block

// Scratch: S[b][h][q][j] with j-stride NJP. 4*8*1024*36 floats = 4.7MB.
__device__ float g_S[B_ * H_ * LQ * NJP];

// ---------------------------------------------------------------------------
// Kernel 1: S[b,h,q,j] = dot(query[b,h,q,:], rel_table[j,:])
// grid (LQ/64, H, B) = 512 blocks, block (9,16)=144. Tile: 4q x 4j.
// Inner loop per d: 1 LDS.128 (tT) + 4 scalar LDS (qS) + 16 FMA.
// ---------------------------------------------------------------------------
__global__ void __launch_bounds__(144) compute_s_kernel(
    const float* __restrict__ query,
    const float* __restrict__ table)
{
    __shared__ float qS[QROWS][DH + 1];  // +1 pad: conflict-free column reads
    __shared__ float tT[DH][NJP];        // transposed table, j-contiguous

    const int tid   = threadIdx.y * 9 + threadIdx.x;
    const int qBase = blockIdx.x * QROWS;
    const int h     = blockIdx.y;
    const int b     = blockIdx.z;

    const float* qptr = query + (size_t)(((b * H_ + h) * LQ) + qBase) * DH;

    // Load 64x64 query tile (1024 float4)
    for (int i = tid; i < QROWS * DH / 4; i += 144) {
        float4 v = ((const float4*)qptr)[i];
        int qr = i >> 4;
        int d0 = (i & 15) << 2;
        qS[qr][d0 + 0] = v.x; qS[qr][d0 + 1] = v.y;
        qS[qr][d0 + 2] = v.z; qS[qr][d0 + 3] = v.w;
    }
    // Load 33x64 table, transposed into tT[d][j] (528 float4)
    for (int i = tid; i < NJ * DH / 4; i += 144) {
        float4 v = ((const float4*)table)[i];
        int j  = i >> 4;
        int d0 = (i & 15) << 2;
        tT[d0 + 0][j] = v.x; tT[d0 + 1][j] = v.y;
        tT[d0 + 2][j] = v.z; tT[d0 + 3][j] = v.w;
    }
    // Zero pad columns j = 33..35
    for (int i = tid; i < DH * 3; i += 144) tT[i / 3][NJ + (i % 3)] = 0.f;
    __syncthreads();

    const int q0 = threadIdx.y * 4;   // 0..60
    const int j0 = threadIdx.x * 4;   // 0..32

    float acc[4][4] = {};
    #pragma unroll 8
    for (int d = 0; d < DH; d++) {
        float4 tv = *(const float4*)(&tT[d][j0]);
        #pragma unroll
        for (int i = 0; i < 4; i++) {
            float qv = qS[q0 + i][d];
            acc[i][0] += qv * tv.x;
            acc[i][1] += qv * tv.y;
            acc[i][2] += qv * tv.z;
            acc[i][3] += qv * tv.w;
        }
    }

    float* sp = g_S + (size_t)(((b * H_ + h) << 10) + qBase + q0) * NJP + j0;
    #pragma unroll
    for (int i = 0; i < 4; i++) {
        float4 o = make_float4(acc[i][0], acc[i][1], acc[i][2], acc[i][3]);
        *(float4*)(sp + i * NJP) = o;
    }
}

// ---------------------------------------------------------------------------
// Kernel 2 (EXACT round-3/6 version, 23.1us known-good, ~write floor):
// out[b,h,q,k] = S[b,h,q, clip(ts[b,k]-ts[b,q],-16,16)+16]
// grid (LQ, B), block 256. Each thread handles 4 consecutive k for all 8 h.
// ---------------------------------------------------------------------------
__global__ void __launch_bounds__(256) gather_kernel(
    const int* __restrict__ time_ids,
    float* __restrict__ out)
{
    __shared__ float s_sm[H_][NJ];

    const int q   = blockIdx.x;
    const int b   = blockIdx.y;
    const int tid = threadIdx.x;

    // H_*NJ = 264 > 256 threads: stride this loop.
    for (int i = tid; i < H_ * NJ; i += 256) {
        int h = i / NJ;
        int j = i - h * NJ;
        s_sm[h][j] = g_S[(size_t)(((b * H_ + h) << 10) + q) * NJP + j];
    }

    const int* tsb = time_ids + b * KL;
    const int  tq  = tsb[q];
    __syncthreads();

    const int k0 = tid * 4;
    int4 tk = *(const int4*)(tsb + k0);

    int i0 = min(max(tk.x - tq, -MAXREL), MAXREL) + MAXREL;
    int i1 = min(max(tk.y - tq, -MAXREL), MAXREL) + MAXREL;
    int i2 = min(max(tk.z - tq, -MAXREL), MAXREL) + MAXREL;
    int i3 = min(max(tk.w - tq, -MAXREL), MAXREL) + MAXREL;

    float* op = out + ((size_t)(b * H_ * LQ + q) << 10) + k0;
    #pragma unroll
    for (int h = 0; h < H_; h++) {
        float4 o = make_float4(s_sm[h][i0], s_sm[h][i1], s_sm[h][i2], s_sm[h][i3]);
        *(float4*)(op + ((size_t)h << 20)) = o;
    }
}

// ---------------------------------------------------------------------------
extern "C" void kernel_launch(void* const* d_in, const int* in_sizes, int n_in,
                              void* d_out, int out_size)
{
    const float* query    = (const float*)d_in[0];   // [4,8,1024,64]
    const float* table    = (const float*)d_in[1];   // [33,64]
    const int*   time_ids = (const int*)d_in[2];     // [4,1024] int32
    float*       out      = (float*)d_out;           // [4,8,1024,1024]

    dim3 g1(LQ / QROWS, H_, B_);
    dim3 b1(9, 16, 1);
    compute_s_kernel<<<g1, b1>>>(query, table);

    dim3 g2(LQ, B_);
    gather_kernel<<<g2, 256>>>(time_ids, out);
}